// round 11
// baseline (speedup 1.0000x reference)
#include <cuda_runtime.h>

// LogSig_var: depth-2 log-signature over 64 segments.
// inp: (B, T, 12) fp32, length: (B,) int32 -> out: (B, 64, 78) fp32
// Block per batch, TPB=512: thread = (segment s, pair-group g in 0..3,
// step-half h in 0..1). Each (s,g) pair of threads sums cross terms over
// half the segment's steps; partials combined with one shfl_xor.

#define D_CH 12
#define NSEG 64
#define TPB 512

__host__ __device__ constexpr int pairI(int p) {
    int i = 0, rem = p;
    while (rem >= 11 - i) { rem -= 11 - i; i++; }
    return i;
}
__host__ __device__ constexpr int pairJ(int p) {
    int i = 0, rem = p;
    while (rem >= 11 - i) { rem -= 11 - i; i++; }
    return i + 1 + rem;
}

// Monotone skew every 16 rows: no overlap; rows 16 apart start 4 banks apart.
__device__ __forceinline__ int srow(int row) {
    return row * 12 + (row >> 4) * 4;
}

struct Row { float v[D_CH]; };

__device__ __forceinline__ void loadRow(const float* sX, int row, Row& r) {
    int base = srow(row);
    float4 a = *(const float4*)(sX + base);
    float4 b = *(const float4*)(sX + base + 4);
    float4 c = *(const float4*)(sX + base + 8);
    r.v[0]=a.x; r.v[1]=a.y; r.v[2]=a.z;  r.v[3]=a.w;
    r.v[4]=b.x; r.v[5]=b.y; r.v[6]=b.z;  r.v[7]=b.w;
    r.v[8]=c.x; r.v[9]=c.y; r.v[10]=c.z; r.v[11]=c.w;
}

// Template recursion: pair indices are compile-time literals -> registers only.
template<int P, int PEND>
struct Pairs {
    static __device__ __forceinline__ void acc(const Row& cur, const Row& nxt, float* a) {
        constexpr int i = pairI(P);
        constexpr int j = pairJ(P);
        float t = a[0];
        t = fmaf(cur.v[i],  nxt.v[j], t);
        t = fmaf(-cur.v[j], nxt.v[i], t);
        a[0] = t;
        Pairs<P + 1, PEND>::acc(cur, nxt, a + 1);
    }
    static __device__ __forceinline__ void comb(float* a) {
        a[0] += __shfl_xor_sync(0xFFFFFFFFu, a[0], 1);
        Pairs<P + 1, PEND>::comb(a + 1);
    }
    static __device__ __forceinline__ void out(float* ob, const Row& xa, const Row& xb,
                                               const float* a) {
        constexpr int i = pairI(P);
        constexpr int j = pairJ(P);
        float cross = xa.v[i] * xb.v[j] - xa.v[j] * xb.v[i];
        ob[D_CH + P] = 0.5f * (a[0] - cross);
        Pairs<P + 1, PEND>::out(ob, xa, xb, a + 1);
    }
};
template<int P>
struct Pairs<P, P> {
    static __device__ __forceinline__ void acc(const Row&, const Row&, float*) {}
    static __device__ __forceinline__ void comb(float*) {}
    static __device__ __forceinline__ void out(float*, const Row&, const Row&, const float*) {}
};

// Sum cross terms for t in [t0, t1). acc must be pre-initialized.
template<bool EXPAND, int P0, int P1>
__device__ __forceinline__ void accum_range(const float* sX, int t0, int t1, int k,
                                            float* acc) {
    if (t0 >= t1) return;
    Row x, y;
    loadRow(sX, EXPAND ? (t0 / k) : t0, x);
    int t = t0;
    for (;;) {
        loadRow(sX, EXPAND ? ((t + 1) / k) : (t + 1), y);
        Pairs<P0, P1>::acc(x, y, acc);
        if (++t >= t1) return;
        loadRow(sX, EXPAND ? ((t + 1) / k) : (t + 1), x);
        Pairs<P0, P1>::acc(y, x, acc);
        if (++t >= t1) return;
    }
}

template<bool EXPAND, int P0, int P1>
__device__ __forceinline__ void do_group(const float* sX, int a, int b, int k,
                                         float* ob, int g, int h) {
    float acc[P1 - P0];
#pragma unroll
    for (int q = 0; q < P1 - P0; q++) acc[q] = 0.0f;

    // Split steps [a,b) between h=0 and h=1 (adjacent lanes).
    const int m = a + ((b - a + 1) >> 1);
    const int t0 = h ? m : a;
    const int t1 = h ? b : m;
    accum_range<EXPAND, P0, P1>(sX, t0, t1, k, acc);

    // Combine partials across the h-pair (lane ^ 1).
    Pairs<P0, P1>::comb(acc);

    if (h == 0) {
        Row xa, xb;
        loadRow(sX, EXPAND ? (a / k) : a, xa);
        loadRow(sX, EXPAND ? (b / k) : b, xb);
        if (g == 0) {
#pragma unroll
            for (int c = 0; c < D_CH; c++) ob[c] = xb.v[c] - xa.v[c];
        }
        Pairs<P0, P1>::out(ob, xa, xb, acc);
    }
}

__global__ __launch_bounds__(TPB, 2)
void logsig_kernel(const float* __restrict__ inp, const int* __restrict__ length,
                   float* __restrict__ out, int T) {
    extern __shared__ float sX[];
    const int blk = blockIdx.x;
    const int L = length[blk];

    // Stage X[0..L) into SMEM (coalesced float4 reads; rows are 48B = 3xfloat4)
    const float4* Xg = (const float4*)(inp + (size_t)blk * T * D_CH);
    const int n4 = L * 3;
    for (int i = threadIdx.x; i < n4; i += TPB) {
        float4 v = Xg[i];
        int row = i / 3;
        int q = i - row * 3;
        *(float4*)&sX[row * 12 + (row >> 4) * 4 + q * 4] = v;
    }
    __syncthreads();

    const bool expand = (L < NSEG + 1);
    const int k    = expand ? (NSEG / L + 1) : 1;
    const int Leff = expand ? (k * L) : L;
    const float Lm1 = (float)(Leff - 1);

    const int s = threadIdx.x >> 3;          // segment 0..63
    const int g = (threadIdx.x >> 1) & 3;    // pair-group 0..3
    const int h = threadIdx.x & 1;           // step-half 0..1

    // tv_j = round(1 + j*(Leff-1)/64); all fp32 intermediates exact (< 2^24),
    // rintf = round-half-to-even matches jnp.round bit-exactly.
    const int a  = (int)rintf(1.0f + ((float)s       * Lm1) * (1.0f / 64.0f)) - 1;
    const int bb = (int)rintf(1.0f + ((float)(s + 1) * Lm1) * (1.0f / 64.0f)) - 1;

    float* ob = out + ((size_t)blk * NSEG + s) * 78;

    if (!expand) {
        switch (g) {
            case 0:  do_group<false,  0, 17>(sX, a, bb, 1, ob, g, h); break;
            case 1:  do_group<false, 17, 34>(sX, a, bb, 1, ob, g, h); break;
            case 2:  do_group<false, 34, 50>(sX, a, bb, 1, ob, g, h); break;
            default: do_group<false, 50, 66>(sX, a, bb, 1, ob, g, h); break;
        }
    } else {
        switch (g) {
            case 0:  do_group<true,  0, 17>(sX, a, bb, k, ob, g, h); break;
            case 1:  do_group<true, 17, 34>(sX, a, bb, k, ob, g, h); break;
            case 2:  do_group<true, 34, 50>(sX, a, bb, k, ob, g, h); break;
            default: do_group<true, 50, 66>(sX, a, bb, k, ob, g, h); break;
        }
    }
}

extern "C" void kernel_launch(void* const* d_in, const int* in_sizes, int n_in,
                              void* d_out, int out_size) {
    const float* inp    = (const float*)d_in[0];
    const int*   length = (const int*)d_in[1];
    float*       out    = (float*)d_out;

    const int B = in_sizes[1];
    const int T = in_sizes[0] / (B * D_CH);

    // SMEM: T rows * 12 floats + monotone skew ((T>>4)*4) + slack
    const size_t smemBytes = (size_t)(T * 12 + (T >> 4) * 4 + 16) * sizeof(float);

    cudaFuncSetAttribute(logsig_kernel,
                         cudaFuncAttributeMaxDynamicSharedMemorySize,
                         (int)smemBytes);

    logsig_kernel<<<B, TPB, smemBytes>>>(inp, length, out, T);
}

// round 12
// speedup vs baseline: 1.0620x; 1.0620x over previous
#include <cuda_runtime.h>

// LogSig_var: depth-2 log-signature over 64 segments.
// inp: (B, T, 12) fp32, length: (B,) int32 -> out: (B, 64, 78) fp32
// Block per batch, TPB=256 (8 warps). WARP-UNIFORM pair-group:
//   wid 0..7: g = wid&3 (same switch branch for all 32 lanes -> no divergence)
//   segment s = (wid>>2)*32 + lane
// Each thread walks its whole segment, accumulating its 16-17 pair cross-sums.

#define D_CH 12
#define NSEG 64
#define TPB 256

__host__ __device__ constexpr int pairI(int p) {
    int i = 0, rem = p;
    while (rem >= 11 - i) { rem -= 11 - i; i++; }
    return i;
}
__host__ __device__ constexpr int pairJ(int p) {
    int i = 0, rem = p;
    while (rem >= 11 - i) { rem -= 11 - i; i++; }
    return i + 1 + rem;
}

// Monotone skew every 32 rows: no overlap; lane-to-lane row delta at L=2048
// (32 rows = 388 floats = 97 16B-quads, 97 mod 8 = 1) covers all 8 quad-banks
// -> conflict-free 4-wavefront LDS.128 (the 512B floor).
__device__ __forceinline__ int srow(int row) {
    return row * 12 + (row >> 5) * 4;
}

struct Row { float v[D_CH]; };

__device__ __forceinline__ void loadRow(const float* sX, int row, Row& r) {
    int base = srow(row);
    float4 a = *(const float4*)(sX + base);
    float4 b = *(const float4*)(sX + base + 4);
    float4 c = *(const float4*)(sX + base + 8);
    r.v[0]=a.x; r.v[1]=a.y; r.v[2]=a.z;  r.v[3]=a.w;
    r.v[4]=b.x; r.v[5]=b.y; r.v[6]=b.z;  r.v[7]=b.w;
    r.v[8]=c.x; r.v[9]=c.y; r.v[10]=c.z; r.v[11]=c.w;
}

// Template recursion: pair indices are compile-time literals -> registers only.
template<int P, int PEND>
struct Pairs {
    static __device__ __forceinline__ void acc(const Row& cur, const Row& nxt, float* a) {
        constexpr int i = pairI(P);
        constexpr int j = pairJ(P);
        float t = a[0];
        t = fmaf(cur.v[i],  nxt.v[j], t);
        t = fmaf(-cur.v[j], nxt.v[i], t);
        a[0] = t;
        Pairs<P + 1, PEND>::acc(cur, nxt, a + 1);
    }
    static __device__ __forceinline__ void out(float* ob, const Row& xa, const Row& xb,
                                               const float* a) {
        constexpr int i = pairI(P);
        constexpr int j = pairJ(P);
        float cross = xa.v[i] * xb.v[j] - xa.v[j] * xb.v[i];
        ob[D_CH + P] = 0.5f * (a[0] - cross);
        Pairs<P + 1, PEND>::out(ob, xa, xb, a + 1);
    }
};
template<int P>
struct Pairs<P, P> {
    static __device__ __forceinline__ void acc(const Row&, const Row&, float*) {}
    static __device__ __forceinline__ void out(float*, const Row&, const Row&, const float*) {}
};

template<bool EXPAND, int P0, int P1, bool WRITE_INC>
__device__ __forceinline__ void segment_work(const float* sX, int a, int b, int k,
                                             float* ob) {
    Row x, y, xa;
    float acc[P1 - P0];
#pragma unroll
    for (int q = 0; q < P1 - P0; q++) acc[q] = 0.0f;

    loadRow(sX, EXPAND ? (a / k) : a, x);
    xa = x;

    int t = a;
    for (;;) {
        loadRow(sX, EXPAND ? ((t + 1) / k) : (t + 1), y);
        Pairs<P0, P1>::acc(x, y, acc);
        t++;
        if (t >= b) break;

        loadRow(sX, EXPAND ? ((t + 1) / k) : (t + 1), x);
        Pairs<P0, P1>::acc(y, x, acc);
        t++;
        if (t >= b) { y = x; break; }
    }
    // y holds X[b]
    if (WRITE_INC) {
#pragma unroll
        for (int c = 0; c < D_CH; c++) ob[c] = y.v[c] - xa.v[c];
    }
    Pairs<P0, P1>::out(ob, xa, y, acc);
}

__global__ __launch_bounds__(TPB, 2)
void logsig_kernel(const float* __restrict__ inp, const int* __restrict__ length,
                   float* __restrict__ out, int T) {
    extern __shared__ float sX[];
    const int blk = blockIdx.x;
    const int L = length[blk];

    // Stage X[0..L) into SMEM (coalesced float4 reads; rows are 48B = 3xfloat4)
    const float4* Xg = (const float4*)(inp + (size_t)blk * T * D_CH);
    const int n4 = L * 3;
    for (int i = threadIdx.x; i < n4; i += TPB) {
        float4 v = Xg[i];
        int row = i / 3;
        int q = i - row * 3;
        *(float4*)&sX[row * 12 + (row >> 5) * 4 + q * 4] = v;
    }
    __syncthreads();

    const bool expand = (L < NSEG + 1);
    const int k    = expand ? (NSEG / L + 1) : 1;
    const int Leff = expand ? (k * L) : L;
    const float Lm1 = (float)(Leff - 1);

    const int wid  = threadIdx.x >> 5;
    const int lane = threadIdx.x & 31;
    const int g = wid & 3;                    // warp-uniform pair-group
    const int s = ((wid >> 2) << 5) + lane;   // segment 0..63

    // tv_j = round(1 + j*(Leff-1)/64); all fp32 intermediates exact (< 2^24),
    // rintf = round-half-to-even matches jnp.round bit-exactly.
    const int a  = (int)rintf(1.0f + ((float)s       * Lm1) * (1.0f / 64.0f)) - 1;
    const int bb = (int)rintf(1.0f + ((float)(s + 1) * Lm1) * (1.0f / 64.0f)) - 1;

    float* ob = out + ((size_t)blk * NSEG + s) * 78;

    if (!expand) {
        switch (g) {   // uniform across the warp: no divergence
            case 0:  segment_work<false,  0, 17, true >(sX, a, bb, 1, ob); break;
            case 1:  segment_work<false, 17, 34, false>(sX, a, bb, 1, ob); break;
            case 2:  segment_work<false, 34, 50, false>(sX, a, bb, 1, ob); break;
            default: segment_work<false, 50, 66, false>(sX, a, bb, 1, ob); break;
        }
    } else {
        switch (g) {
            case 0:  segment_work<true,  0, 17, true >(sX, a, bb, k, ob); break;
            case 1:  segment_work<true, 17, 34, false>(sX, a, bb, k, ob); break;
            case 2:  segment_work<true, 34, 50, false>(sX, a, bb, k, ob); break;
            default: segment_work<true, 50, 66, false>(sX, a, bb, k, ob); break;
        }
    }
}

extern "C" void kernel_launch(void* const* d_in, const int* in_sizes, int n_in,
                              void* d_out, int out_size) {
    const float* inp    = (const float*)d_in[0];
    const int*   length = (const int*)d_in[1];
    float*       out    = (float*)d_out;

    const int B = in_sizes[1];
    const int T = in_sizes[0] / (B * D_CH);

    // SMEM: T rows * 12 floats + monotone skew ((T>>5)*4) + slack
    const size_t smemBytes = (size_t)(T * 12 + (T >> 5) * 4 + 16) * sizeof(float);

    cudaFuncSetAttribute(logsig_kernel,
                         cudaFuncAttributeMaxDynamicSharedMemorySize,
                         (int)smemBytes);

    logsig_kernel<<<B, TPB, smemBytes>>>(inp, length, out, T);
}

// round 14
// speedup vs baseline: 2.1080x; 1.9849x over previous
#include <cuda_runtime.h>

// LogSig_var: depth-2 log-signature over 64 segments.
// inp: (B, T, 12) fp32, length: (B,) int32 -> out: (B, 64, 78) fp32
//
// 4 blocks per batch (grid = 4B), TPB=128. Block q handles segments
// [16q, 16q+16) and stages only rows [rowLo, rowHi] of the path (~L/4).
// Warp = pair-group g (warp-uniform switch). Lane = (segment local 0..15,
// step-half h in 0..1); the two halves' partial cross-sums combine with one
// shfl_xor(16). Kills the load-imbalance tail (big-L blocks were serial).

#define D_CH 12
#define NSEG 64
#define TPB 128

__host__ __device__ constexpr int pairI(int p) {
    int i = 0, rem = p;
    while (rem >= 11 - i) { rem -= 11 - i; i++; }
    return i;
}
__host__ __device__ constexpr int pairJ(int p) {
    int i = 0, rem = p;
    while (rem >= 11 - i) { rem -= 11 - i; i++; }
    return i + 1 + rem;
}

// Monotone skew every 32 local rows: no overlap, decorrelates the ~32-row
// lane stride (97 16B-quads ~ 1 mod 8 -> all quad-banks covered).
__device__ __forceinline__ int srow(int row) {
    return row * 12 + (row >> 5) * 4;
}

struct Row { float v[D_CH]; };

__device__ __forceinline__ void loadRow(const float* sX, int row, Row& r) {
    int base = srow(row);
    float4 a = *(const float4*)(sX + base);
    float4 b = *(const float4*)(sX + base + 4);
    float4 c = *(const float4*)(sX + base + 8);
    r.v[0]=a.x; r.v[1]=a.y; r.v[2]=a.z;  r.v[3]=a.w;
    r.v[4]=b.x; r.v[5]=b.y; r.v[6]=b.z;  r.v[7]=b.w;
    r.v[8]=c.x; r.v[9]=c.y; r.v[10]=c.z; r.v[11]=c.w;
}

// Template recursion: pair indices are compile-time literals -> registers only.
template<int P, int PEND>
struct Pairs {
    static __device__ __forceinline__ void acc(const Row& cur, const Row& nxt, float* a) {
        constexpr int i = pairI(P);
        constexpr int j = pairJ(P);
        float t = a[0];
        t = fmaf(cur.v[i],  nxt.v[j], t);
        t = fmaf(-cur.v[j], nxt.v[i], t);
        a[0] = t;
        Pairs<P + 1, PEND>::acc(cur, nxt, a + 1);
    }
    static __device__ __forceinline__ void comb(float* a) {
        a[0] += __shfl_xor_sync(0xFFFFFFFFu, a[0], 16);
        Pairs<P + 1, PEND>::comb(a + 1);
    }
    static __device__ __forceinline__ void out(float* ob, const Row& xa, const Row& xb,
                                               const float* a) {
        constexpr int i = pairI(P);
        constexpr int j = pairJ(P);
        float cross = xa.v[i] * xb.v[j] - xa.v[j] * xb.v[i];
        ob[D_CH + P] = 0.5f * (a[0] - cross);
        Pairs<P + 1, PEND>::out(ob, xa, xb, a + 1);
    }
};
template<int P>
struct Pairs<P, P> {
    static __device__ __forceinline__ void acc(const Row&, const Row&, float*) {}
    static __device__ __forceinline__ void comb(float*) {}
    static __device__ __forceinline__ void out(float*, const Row&, const Row&, const float*) {}
};

// Sum cross terms for t in [t0, t1); rows indexed relative to rowLo.
template<bool EXPAND, int P0, int P1>
__device__ __forceinline__ void accum_range(const float* sX, int t0, int t1,
                                            int k, int rowLo, float* acc) {
    if (t0 >= t1) return;
    Row x, y;
    loadRow(sX, (EXPAND ? (t0 / k) : t0) - rowLo, x);
    int t = t0;
    for (;;) {
        loadRow(sX, (EXPAND ? ((t + 1) / k) : (t + 1)) - rowLo, y);
        Pairs<P0, P1>::acc(x, y, acc);
        if (++t >= t1) return;
        loadRow(sX, (EXPAND ? ((t + 1) / k) : (t + 1)) - rowLo, x);
        Pairs<P0, P1>::acc(y, x, acc);
        if (++t >= t1) return;
    }
}

template<bool EXPAND, int P0, int P1, bool WRITE_INC>
__device__ __forceinline__ void do_group(const float* sX, int a, int b, int k,
                                         int rowLo, float* ob, int h) {
    float acc[P1 - P0];
#pragma unroll
    for (int q = 0; q < P1 - P0; q++) acc[q] = 0.0f;

    // Split steps [a,b) between h=0 and h=1 (lanes 16 apart).
    const int m = a + ((b - a + 1) >> 1);
    accum_range<EXPAND, P0, P1>(sX, h ? m : a, h ? b : m, k, rowLo, acc);

    Pairs<P0, P1>::comb(acc);

    if (h == 0) {
        Row xa, xb;
        loadRow(sX, (EXPAND ? (a / k) : a) - rowLo, xa);
        loadRow(sX, (EXPAND ? (b / k) : b) - rowLo, xb);
        if (WRITE_INC) {
#pragma unroll
            for (int c = 0; c < D_CH; c++) ob[c] = xb.v[c] - xa.v[c];
        }
        Pairs<P0, P1>::out(ob, xa, xb, acc);
    }
}

__global__ __launch_bounds__(TPB, 6)
void logsig_kernel(const float* __restrict__ inp, const int* __restrict__ length,
                   float* __restrict__ out, int T) {
    extern __shared__ float sX[];
    const int blk = blockIdx.x >> 2;        // batch
    const int qb  = blockIdx.x & 3;         // segment-quarter 0..3
    const int L = length[blk];

    const bool expand = (L < NSEG + 1);
    const int k    = expand ? (NSEG / L + 1) : 1;
    const int Leff = expand ? (k * L) : L;
    const float Lm1 = (float)(Leff - 1);
    const int s0 = qb << 4;                 // first segment of this block

    // Block-level step range [aB, bB] -> row range to stage.
    // tv_j = round(1 + j*(Leff-1)/64); exact fp32, rintf == jnp.round.
    const int aB = (int)rintf(1.0f + ((float)s0        * Lm1) * (1.0f / 64.0f)) - 1;
    const int bB = (int)rintf(1.0f + ((float)(s0 + 16) * Lm1) * (1.0f / 64.0f)) - 1;
    const int rowLo = expand ? 0 : aB;
    const int rowHi = expand ? (L - 1) : bB;

    // Stage rows [rowLo, rowHi] (coalesced float4; rows are 3 quads).
    const float4* Xg = (const float4*)(inp + (size_t)blk * T * D_CH);
    const int n4 = (rowHi - rowLo + 1) * 3;
    const int g0 = rowLo * 3;
    for (int i = threadIdx.x; i < n4; i += TPB) {
        float4 v = Xg[g0 + i];
        int row = i / 3;
        int q = i - row * 3;
        *(float4*)&sX[row * 12 + (row >> 5) * 4 + q * 4] = v;
    }
    __syncthreads();

    const int wid  = threadIdx.x >> 5;      // 0..3 = pair-group (warp-uniform)
    const int lane = threadIdx.x & 31;
    const int h = lane >> 4;                // step-half
    const int s = s0 + (lane & 15);         // segment

    const int a  = (int)rintf(1.0f + ((float)s       * Lm1) * (1.0f / 64.0f)) - 1;
    const int bb = (int)rintf(1.0f + ((float)(s + 1) * Lm1) * (1.0f / 64.0f)) - 1;

    float* ob = out + ((size_t)blk * NSEG + s) * 78;

    if (!expand) {
        switch (wid) {   // uniform across the warp
            case 0:  do_group<false,  0, 17, true >(sX, a, bb, 1, rowLo, ob, h); break;
            case 1:  do_group<false, 17, 34, false>(sX, a, bb, 1, rowLo, ob, h); break;
            case 2:  do_group<false, 34, 50, false>(sX, a, bb, 1, rowLo, ob, h); break;
            default: do_group<false, 50, 66, false>(sX, a, bb, 1, rowLo, ob, h); break;
        }
    } else {
        switch (wid) {
            case 0:  do_group<true,  0, 17, true >(sX, a, bb, k, rowLo, ob, h); break;
            case 1:  do_group<true, 17, 34, false>(sX, a, bb, k, rowLo, ob, h); break;
            case 2:  do_group<true, 34, 50, false>(sX, a, bb, k, rowLo, ob, h); break;
            default: do_group<true, 50, 66, false>(sX, a, bb, k, rowLo, ob, h); break;
        }
    }
}

extern "C" void kernel_launch(void* const* d_in, const int* in_sizes, int n_in,
                              void* d_out, int out_size) {
    const float* inp    = (const float*)d_in[0];
    const int*   length = (const int*)d_in[1];
    float*       out    = (float*)d_out;

    const int B = in_sizes[1];
    const int T = in_sizes[0] / (B * D_CH);

    // Max staged rows per block: ~T/4 + 2 (non-expand quarter) with skew.
    const int maxRows = T / 4 + 4;
    const size_t smemBytes =
        (size_t)(maxRows * 12 + (maxRows >> 5) * 4 + 16) * sizeof(float);

    cudaFuncSetAttribute(logsig_kernel,
                         cudaFuncAttributeMaxDynamicSharedMemorySize,
                         (int)smemBytes);

    logsig_kernel<<<B * 4, TPB, smemBytes>>>(inp, length, out, T);
}